// round 8
// baseline (speedup 1.0000x reference)
#include <cuda_runtime.h>

// ---------------- problem constants ----------------
#define NMAX 50000
#define EMAX 800000
#define D    128
#define DLAT 64
#define BN_EPS 1e-5f
#define SCAN_B 256
#define NBLK ((NMAX + SCAN_B - 1) / SCAN_B)

// ---------------- packed f32x2 helpers (Blackwell double-rate fp32) --------
__device__ __forceinline__ unsigned long long pack2(float lo, float hi) {
    unsigned long long r;
    asm("mov.b64 %0, {%1, %2};" : "=l"(r) : "f"(lo), "f"(hi));
    return r;
}
__device__ __forceinline__ unsigned long long fma2(unsigned long long a,
                                                   unsigned long long b,
                                                   unsigned long long c) {
    unsigned long long d;
    asm("fma.rn.f32x2 %0, %1, %2, %3;" : "=l"(d) : "l"(a), "l"(b), "l"(c));
    return d;
}
__device__ __forceinline__ void unpack2(unsigned long long v, float& lo, float& hi) {
    asm("mov.b64 {%0, %1}, %2;" : "=f"(lo), "=f"(hi) : "l"(v));
}

// ---------------- cp.async helpers ----------------
__device__ __forceinline__ void cp_async16(void* smem_dst, const void* gmem_src) {
    unsigned smem = (unsigned)__cvta_generic_to_shared(smem_dst);
    asm volatile("cp.async.ca.shared.global [%0], [%1], 16;\n"
                 :: "r"(smem), "l"(__cvta_generic_to_global(gmem_src)));
}
__device__ __forceinline__ void cp_commit() {
    asm volatile("cp.async.commit_group;\n");
}
__device__ __forceinline__ void cp_wait0() {
    asm volatile("cp.async.wait_group 0;\n");
}

// ---------------- scratch (device globals; no allocation) ----------------
__device__ int   g_cnt[NMAX];
__device__ int   g_rowptr[NMAX + 1];
__device__ int   g_cursor[NMAX];
__device__ int   g_srcs[EMAX];
__device__ float g_w[EMAX];
__device__ int   g_bsum[NBLK];
__device__ int   g_boff[NBLK];
__device__ float g_isd[NMAX];
__device__ float g_invdeg[NMAX];
__device__ float g_h0[(size_t)NMAX * D];
__device__ float g_h [(size_t)NMAX * D];
__device__ float g_aggh[(size_t)NMAX * D];
__device__ float g_sum[D];
__device__ float g_sumsq[D];
__device__ float g_scale[D];
__device__ float g_shift[D];
__device__ float g_Wcat[D * D];
__device__ float g_bcat[D];

// ---------------- init: zero counters/accums, build Wcat/bcat ----------------
__global__ void k_init(const float* __restrict__ Wmu, const float* __restrict__ Wls,
                       const float* __restrict__ bmu, const float* __restrict__ bls,
                       int N) {
    int i = blockIdx.x * blockDim.x + threadIdx.x;
    if (i < N) g_cnt[i] = 0;
    if (i < D) {
        g_sum[i] = 0.0f;
        g_sumsq[i] = 0.0f;
        g_bcat[i] = (i < DLAT) ? bmu[i] : bls[i - DLAT];
    }
    if (i < D * D) {
        int k = i >> 7;
        int j = i & 127;
        g_Wcat[i] = (j < DLAT) ? Wmu[k * DLAT + j] : Wls[k * DLAT + (j - DLAT)];
    }
}

// ---------------- degree count over dst ----------------
__global__ void k_count(const int* __restrict__ ei, int E) {
    int e = blockIdx.x * blockDim.x + threadIdx.x;
    if (e < E) atomicAdd(&g_cnt[ei[E + e]], 1);
}

// ---------------- scan phase A: block sums + degree-derived values ----------
__global__ void __launch_bounds__(SCAN_B) k_scanA(int N) {
    __shared__ int ws[8];
    int i = blockIdx.x * SCAN_B + threadIdx.x;
    int v = (i < N) ? g_cnt[i] : 0;
    if (i < N) {
        float d = (float)v + 1.0f;
        g_isd[i] = rsqrtf(d);
        g_invdeg[i] = 1.0f / d;
    }
    int lane = threadIdx.x & 31, wid = threadIdx.x >> 5;
    int r = v;
#pragma unroll
    for (int o = 16; o; o >>= 1) r += __shfl_down_sync(0xffffffffu, r, o);
    if (lane == 0) ws[wid] = r;
    __syncthreads();
    if (threadIdx.x < 8) {
        int t = ws[threadIdx.x];
#pragma unroll
        for (int o = 4; o; o >>= 1) t += __shfl_down_sync(0xffu, t, o);
        if (threadIdx.x == 0) g_bsum[blockIdx.x] = t;
    }
}

// ---------------- scan phase B: exclusive scan of block sums (nb<=256) ------
__global__ void __launch_bounds__(SCAN_B) k_scanB(int nb, int E, int N) {
    __shared__ int ws[8];
    int tid = threadIdx.x;
    int v = (tid < nb) ? g_bsum[tid] : 0;
    int lane = tid & 31, wid = tid >> 5;
    int x = v;
#pragma unroll
    for (int o = 1; o < 32; o <<= 1) {
        int n = __shfl_up_sync(0xffffffffu, x, o);
        if (lane >= o) x += n;
    }
    if (lane == 31) ws[wid] = x;
    __syncthreads();
    if (wid == 0 && lane < 8) {
        int t = ws[lane];
#pragma unroll
        for (int o = 1; o < 8; o <<= 1) {
            int n = __shfl_up_sync(0xffu, t, o);
            if (lane >= o) t += n;
        }
        ws[lane] = t;
    }
    __syncthreads();
    int incl = x + (wid > 0 ? ws[wid - 1] : 0);
    if (tid < nb) g_boff[tid] = incl - v;
    if (tid == 0) g_rowptr[N] = E;
}

// ---------------- scan phase C: local exclusive scan + offset ---------------
__global__ void __launch_bounds__(SCAN_B) k_scanC(int N) {
    __shared__ int ws[8];
    int i = blockIdx.x * SCAN_B + threadIdx.x;
    int v = (i < N) ? g_cnt[i] : 0;
    int lane = threadIdx.x & 31, wid = threadIdx.x >> 5;
    int x = v;
#pragma unroll
    for (int o = 1; o < 32; o <<= 1) {
        int n = __shfl_up_sync(0xffffffffu, x, o);
        if (lane >= o) x += n;
    }
    if (lane == 31) ws[wid] = x;
    __syncthreads();
    if (wid == 0 && lane < 8) {
        int t = ws[lane];
#pragma unroll
        for (int o = 1; o < 8; o <<= 1) {
            int n = __shfl_up_sync(0xffu, t, o);
            if (lane >= o) t += n;
        }
        ws[lane] = t;
    }
    __syncthreads();
    int ex = x - v + (wid > 0 ? ws[wid - 1] : 0) + g_boff[blockIdx.x];
    if (i < N) {
        g_rowptr[i] = ex;
        g_cursor[i] = ex;
    }
}

// ---------------- scatter edges into CSR slots ----------------
__global__ void k_scatter(const int* __restrict__ ei, int E) {
    int e = blockIdx.x * blockDim.x + threadIdx.x;
    if (e < E) {
        int s = ei[e];
        int d = ei[E + e];
        int pos = atomicAdd(&g_cursor[d], 1);
        g_srcs[pos] = s;
        g_w[pos] = g_isd[s] * g_isd[d];
    }
}

// ---------------- GEMM: C[M,128] = A[M,128] @ B[128,128] -------------------
// BK=32 double-buffered, cp.async(B), reg-staged A, f32x2 FMA, LDS.64 B pairs.
// MODE 0: A=x, B=W1           -> g_h0 = raw
// MODE 1: A=g_aggh, B=g_Wcat  -> out_mu / out_ls = raw + bcat (split)
#define BK 32
template <int MODE>
__global__ void __launch_bounds__(128) k_gemm(const float* __restrict__ Aext,
                                              const float* __restrict__ Bext,
                                              int M,
                                              float* __restrict__ out_mu,
                                              float* __restrict__ out_ls) {
    __shared__ float  As[2][BK][68];       // transposed A tiles
    __shared__ float4 Bs[2][BK * 32];      // BK k-rows x 32 float4 (128 floats)

    const float* A = (MODE == 0) ? Aext : g_aggh;
    const float* B = (MODE == 0) ? Bext : g_Wcat;

    int tid = threadIdx.x;
    int tx = tid & 15;
    int ty = tid >> 4;
    int row0 = blockIdx.x * 64;

    // A-load geometry: 4 fragments per thread (64 rows x 32 k = 512 float4)
    int fr[4], fk[4];
#pragma unroll
    for (int li = 0; li < 4; li++) {
        int f = tid * 4 + li;
        fr[li] = f >> 3;          // row 0..63
        fk[li] = (f & 7) * 4;     // k offset 0..28
    }

    unsigned long long accp[8][4];
#pragma unroll
    for (int i = 0; i < 8; i++)
#pragma unroll
        for (int j = 0; j < 4; j++) accp[i][j] = 0ull;

    // ---- prologue: stage 0 ----
    {
#pragma unroll
        for (int j = 0; j < 8; j++)
            cp_async16(&Bs[0][tid + 128 * j], (const float4*)B + tid + 128 * j);
        cp_commit();
#pragma unroll
        for (int li = 0; li < 4; li++) {
            float4 a = make_float4(0.f, 0.f, 0.f, 0.f);
            if (row0 + fr[li] < M)
                a = *(const float4*)&A[(size_t)(row0 + fr[li]) * D + fk[li]];
            As[0][fk[li] + 0][fr[li]] = a.x;
            As[0][fk[li] + 1][fr[li]] = a.y;
            As[0][fk[li] + 2][fr[li]] = a.z;
            As[0][fk[li] + 3][fr[li]] = a.w;
        }
        cp_wait0();
        __syncthreads();
    }

    for (int k0 = 0; k0 < D; k0 += BK) {
        int s = (k0 / BK) & 1;
        int ns = s ^ 1;
        bool pf = (k0 + BK < D);

        float4 areg[4];
        if (pf) {
#pragma unroll
            for (int j = 0; j < 8; j++)
                cp_async16(&Bs[ns][tid + 128 * j],
                           (const float4*)(B + (size_t)(k0 + BK) * D) + tid + 128 * j);
            cp_commit();
#pragma unroll
            for (int li = 0; li < 4; li++) {
                areg[li] = make_float4(0.f, 0.f, 0.f, 0.f);
                if (row0 + fr[li] < M)
                    areg[li] = *(const float4*)&A[(size_t)(row0 + fr[li]) * D + k0 + BK + fk[li]];
            }
        }

        // ---- compute on stage s ----
#pragma unroll
        for (int k = 0; k < BK; k++) {
            float4 av0 = *(float4*)&As[s][k][ty * 8];
            float4 av1 = *(float4*)&As[s][k][ty * 8 + 4];
            const float* brow = (const float*)&Bs[s][k * 32];
            unsigned long long bp[4];
#pragma unroll
            for (int j = 0; j < 4; j++)
                bp[j] = *(const unsigned long long*)&brow[tx * 8 + 2 * j];
            float a[8] = {av0.x, av0.y, av0.z, av0.w, av1.x, av1.y, av1.z, av1.w};
#pragma unroll
            for (int i = 0; i < 8; i++) {
                unsigned long long ap = pack2(a[i], a[i]);
#pragma unroll
                for (int j = 0; j < 4; j++)
                    accp[i][j] = fma2(ap, bp[j], accp[i][j]);
            }
        }

        if (pf) {
#pragma unroll
            for (int li = 0; li < 4; li++) {
                As[ns][fk[li] + 0][fr[li]] = areg[li].x;
                As[ns][fk[li] + 1][fr[li]] = areg[li].y;
                As[ns][fk[li] + 2][fr[li]] = areg[li].z;
                As[ns][fk[li] + 3][fr[li]] = areg[li].w;
            }
            cp_wait0();
        }
        __syncthreads();
    }

    int colbase = tx * 8;
#pragma unroll
    for (int i = 0; i < 8; i++) {
        int row = row0 + ty * 8 + i;
        if (row < M) {
            float4 v0, v1;
            unpack2(accp[i][0], v0.x, v0.y);
            unpack2(accp[i][1], v0.z, v0.w);
            unpack2(accp[i][2], v1.x, v1.y);
            unpack2(accp[i][3], v1.z, v1.w);
            if (MODE == 0) {
                *(float4*)&g_h0[(size_t)row * D + colbase]     = v0;
                *(float4*)&g_h0[(size_t)row * D + colbase + 4] = v1;
            } else {
                float4 bi0 = *(const float4*)&g_bcat[colbase];
                float4 bi1 = *(const float4*)&g_bcat[colbase + 4];
                v0.x += bi0.x; v0.y += bi0.y; v0.z += bi0.z; v0.w += bi0.w;
                v1.x += bi1.x; v1.y += bi1.y; v1.z += bi1.z; v1.w += bi1.w;
                if (colbase < DLAT) {
                    *(float4*)&out_mu[(size_t)row * DLAT + colbase]     = v0;
                    *(float4*)&out_mu[(size_t)row * DLAT + colbase + 4] = v1;
                } else {
                    *(float4*)&out_ls[(size_t)row * DLAT + colbase - DLAT]     = v0;
                    *(float4*)&out_ls[(size_t)row * DLAT + colbase - DLAT + 4] = v1;
                }
            }
        }
    }
}

// ---------------- CSR aggregation: warp per node, no output atomics -------
// MODE 0: g_h[i]   = sum_e w*g_h0[src] + invdeg[i]*g_h0[i] + b1  (+ fused BN partials)
// MODE 1: g_aggh[i]= sum_e w*BN(g_h[src]) + invdeg[i]*BN(g_h[i])   (BN+ReLU fused)
template <int MODE>
__global__ void __launch_bounds__(256) k_agg(const float* __restrict__ b1, int N) {
    __shared__ float sh_s[D];
    __shared__ float sh_s2[D];
    if (MODE == 0) {
        if (threadIdx.x < D) { sh_s[threadIdx.x] = 0.f; sh_s2[threadIdx.x] = 0.f; }
        __syncthreads();
    }

    int gwarp = (blockIdx.x * blockDim.x + threadIdx.x) >> 5;
    int lane = threadIdx.x & 31;
    const float* feat = (MODE == 0) ? g_h0 : g_h;

    // per-lane BN scale/shift (MODE 1 only)
    float4 scf, shf;
    if (MODE == 1) {
        scf = ((const float4*)g_scale)[lane];
        shf = ((const float4*)g_shift)[lane];
    }

    float4 acc = make_float4(0.f, 0.f, 0.f, 0.f);
    bool active = (gwarp < N);
    if (active) {
        int node = gwarp;
        int beg = g_rowptr[node];
        int end = g_rowptr[node + 1];
        float id = g_invdeg[node];

        float4 self = *(const float4*)&feat[(size_t)node * D + lane * 4];
        if (MODE == 1) {
            self.x = fmaxf(fmaf(self.x, scf.x, shf.x), 0.0f);
            self.y = fmaxf(fmaf(self.y, scf.y, shf.y), 0.0f);
            self.z = fmaxf(fmaf(self.z, scf.z, shf.z), 0.0f);
            self.w = fmaxf(fmaf(self.w, scf.w, shf.w), 0.0f);
        }
        acc.x = self.x * id; acc.y = self.y * id;
        acc.z = self.z * id; acc.w = self.w * id;
        if (MODE == 0) {
            float4 bi = *(const float4*)&b1[lane * 4];
            acc.x += bi.x; acc.y += bi.y; acc.z += bi.z; acc.w += bi.w;
        }

        for (int base = beg; base < end; base += 32) {
            int t = base + lane;
            int s = 0; float w = 0.f;
            if (t < end) { s = g_srcs[t]; w = g_w[t]; }
            int m = min(32, end - base);
            for (int j = 0; j < m; j++) {
                int sj = __shfl_sync(0xffffffffu, s, j);
                float wj = __shfl_sync(0xffffffffu, w, j);
                float4 v = *(const float4*)&feat[(size_t)sj * D + lane * 4];
                if (MODE == 1) {
                    v.x = fmaxf(fmaf(v.x, scf.x, shf.x), 0.0f);
                    v.y = fmaxf(fmaf(v.y, scf.y, shf.y), 0.0f);
                    v.z = fmaxf(fmaf(v.z, scf.z, shf.z), 0.0f);
                    v.w = fmaxf(fmaf(v.w, scf.w, shf.w), 0.0f);
                }
                acc.x = fmaf(wj, v.x, acc.x);
                acc.y = fmaf(wj, v.y, acc.y);
                acc.z = fmaf(wj, v.z, acc.z);
                acc.w = fmaf(wj, v.w, acc.w);
            }
        }

        float* out = (MODE == 0) ? g_h : g_aggh;
        *(float4*)&out[(size_t)gwarp * D + lane * 4] = acc;
    }

    if (MODE == 0) {
        if (active) {
            int c = lane * 4;
            atomicAdd(&sh_s[c + 0], acc.x);  atomicAdd(&sh_s2[c + 0], acc.x * acc.x);
            atomicAdd(&sh_s[c + 1], acc.y);  atomicAdd(&sh_s2[c + 1], acc.y * acc.y);
            atomicAdd(&sh_s[c + 2], acc.z);  atomicAdd(&sh_s2[c + 2], acc.z * acc.z);
            atomicAdd(&sh_s[c + 3], acc.w);  atomicAdd(&sh_s2[c + 3], acc.w * acc.w);
        }
        __syncthreads();
        if (threadIdx.x < D) {
            atomicAdd(&g_sum[threadIdx.x], sh_s[threadIdx.x]);
            atomicAdd(&g_sumsq[threadIdx.x], sh_s2[threadIdx.x]);
        }
    }
}

// ---------------- BN finalize ----------------
__global__ void k_bnfin(const float* __restrict__ gamma, const float* __restrict__ beta, int N) {
    int c = threadIdx.x;
    float invN = 1.0f / (float)N;
    float mean = g_sum[c] * invN;
    float var = fmaxf(g_sumsq[c] * invN - mean * mean, 0.0f);
    float sc = gamma[c] * rsqrtf(var + BN_EPS);
    g_scale[c] = sc;
    g_shift[c] = beta[c] - mean * sc;
}

// ---------------- launch ----------------
extern "C" void kernel_launch(void* const* d_in, const int* in_sizes, int n_in,
                              void* d_out, int out_size) {
    const float* x     = (const float*)d_in[0];
    const int*   ei    = (const int*)d_in[1];     // int32
    const float* W1    = (const float*)d_in[2];
    const float* b1    = (const float*)d_in[3];
    const float* gamma = (const float*)d_in[4];
    const float* beta  = (const float*)d_in[5];
    const float* Wmu   = (const float*)d_in[6];
    const float* bmu   = (const float*)d_in[7];
    const float* Wls   = (const float*)d_in[8];
    const float* bls   = (const float*)d_in[9];

    int N = in_sizes[0] / D;
    int E = in_sizes[1] / 2;

    float* out_mu = (float*)d_out;
    float* out_ls = (float*)d_out + (size_t)N * DLAT;

    int init_threads = (N > D * D) ? N : D * D;
    int nb = (N + SCAN_B - 1) / SCAN_B;
    int gemm_blocks = (N + 63) / 64;
    int agg_blocks = (N + 7) / 8;

    // --- CSR build; gemm0 stays 4th so the profiler slot lands on it ---
    k_init<<<(init_threads + 255) / 256, 256>>>(Wmu, Wls, bmu, bls, N);   // 1
    k_count<<<(E + 255) / 256, 256>>>(ei, E);                             // 2
    k_scanA<<<nb, SCAN_B>>>(N);                                           // 3
    k_gemm<0><<<gemm_blocks, 128>>>(x, W1, N, nullptr, nullptr);          // 4 (profiled)
    k_scanB<<<1, SCAN_B>>>(nb, E, N);                                     // 5
    k_scanC<<<nb, SCAN_B>>>(N);                                           // 6
    k_scatter<<<(E + 255) / 256, 256>>>(ei, E);                           // 7

    // --- conv1 aggregation (+fused BN stats) ---
    k_agg<0><<<agg_blocks, 256>>>(b1, N);

    // --- BatchNorm finalize (apply is fused into k_agg<1>) ---
    k_bnfin<<<1, 128>>>(gamma, beta, N);

    // --- conv2: aggregate BN(h) (fused), then fused [Wmu|Wls] GEMM ---
    k_agg<1><<<agg_blocks, 256>>>(nullptr, N);
    k_gemm<1><<<gemm_blocks, 128>>>(nullptr, nullptr, N, out_mu, out_ls);
}

// round 9
// speedup vs baseline: 1.0466x; 1.0466x over previous
#include <cuda_runtime.h>

// ---------------- problem constants ----------------
#define NMAX 50000
#define EMAX 800000
#define D    128
#define DLAT 64
#define BN_EPS 1e-5f
#define SCAN_B 256
#define NBLK ((NMAX + SCAN_B - 1) / SCAN_B)

// ---------------- packed f32x2 helpers (Blackwell double-rate fp32) --------
__device__ __forceinline__ unsigned long long pack2(float lo, float hi) {
    unsigned long long r;
    asm("mov.b64 %0, {%1, %2};" : "=l"(r) : "f"(lo), "f"(hi));
    return r;
}
__device__ __forceinline__ unsigned long long fma2(unsigned long long a,
                                                   unsigned long long b,
                                                   unsigned long long c) {
    unsigned long long d;
    asm("fma.rn.f32x2 %0, %1, %2, %3;" : "=l"(d) : "l"(a), "l"(b), "l"(c));
    return d;
}
__device__ __forceinline__ void unpack2(unsigned long long v, float& lo, float& hi) {
    asm("mov.b64 {%0, %1}, %2;" : "=f"(lo), "=f"(hi) : "l"(v));
}

// ---------------- cp.async helpers ----------------
__device__ __forceinline__ void cp_async16(void* smem_dst, const void* gmem_src) {
    unsigned smem = (unsigned)__cvta_generic_to_shared(smem_dst);
    asm volatile("cp.async.ca.shared.global [%0], [%1], 16;\n"
                 :: "r"(smem), "l"(__cvta_generic_to_global(gmem_src)));
}
__device__ __forceinline__ void cp_commit() {
    asm volatile("cp.async.commit_group;\n");
}
__device__ __forceinline__ void cp_wait0() {
    asm volatile("cp.async.wait_group 0;\n");
}

// ---------------- scratch (device globals; no allocation) ----------------
__device__ int   g_cnt[NMAX];
__device__ int   g_rowptr[NMAX + 1];
__device__ int   g_cursor[NMAX];
__device__ int   g_srcs[EMAX];
__device__ float g_w[EMAX];
__device__ int   g_bsum[NBLK];
__device__ float g_isd[NMAX];
__device__ float g_invdeg[NMAX];
__device__ float g_h0[(size_t)NMAX * D];
__device__ float g_h [(size_t)NMAX * D];
__device__ float g_aggh[(size_t)NMAX * D];
__device__ float g_sum[D];
__device__ float g_sumsq[D];
__device__ float g_scale[D];
__device__ float g_shift[D];
__device__ float g_Wcat[D * D];
__device__ float g_bcat[D];

// ---------------- init: zero counters/accums, build Wcat/bcat ----------------
__global__ void k_init(const float* __restrict__ Wmu, const float* __restrict__ Wls,
                       const float* __restrict__ bmu, const float* __restrict__ bls,
                       int N) {
    int i = blockIdx.x * blockDim.x + threadIdx.x;
    if (i < N) g_cnt[i] = 0;
    if (i < D) {
        g_sum[i] = 0.0f;
        g_sumsq[i] = 0.0f;
        g_bcat[i] = (i < DLAT) ? bmu[i] : bls[i - DLAT];
    }
    if (i < D * D) {
        int k = i >> 7;
        int j = i & 127;
        g_Wcat[i] = (j < DLAT) ? Wmu[k * DLAT + j] : Wls[k * DLAT + (j - DLAT)];
    }
}

// ---------------- degree count over dst ----------------
__global__ void k_count(const int* __restrict__ ei, int E) {
    int e = blockIdx.x * blockDim.x + threadIdx.x;
    if (e < E) atomicAdd(&g_cnt[ei[E + e]], 1);
}

// ---------------- scan phase A: block sums + degree-derived values ----------
__global__ void __launch_bounds__(SCAN_B) k_scanA(int N) {
    __shared__ int ws[8];
    int i = blockIdx.x * SCAN_B + threadIdx.x;
    int v = (i < N) ? g_cnt[i] : 0;
    if (i < N) {
        float d = (float)v + 1.0f;
        g_isd[i] = rsqrtf(d);
        g_invdeg[i] = 1.0f / d;
    }
    int lane = threadIdx.x & 31, wid = threadIdx.x >> 5;
    int r = v;
#pragma unroll
    for (int o = 16; o; o >>= 1) r += __shfl_down_sync(0xffffffffu, r, o);
    if (lane == 0) ws[wid] = r;
    __syncthreads();
    if (threadIdx.x < 8) {
        int t = ws[threadIdx.x];
#pragma unroll
        for (int o = 4; o; o >>= 1) t += __shfl_down_sync(0xffu, t, o);
        if (threadIdx.x == 0) g_bsum[blockIdx.x] = t;
    }
}

// ---------------- scan phase B+C merged: every block scans the block sums ---
// (nb <= 256) then does its local exclusive scan with that offset.
__global__ void __launch_bounds__(SCAN_B) k_scanBC(int nb, int E, int N) {
    __shared__ int ws[8];
    __shared__ int s_boff;
    int tid = threadIdx.x;
    int lane = tid & 31, wid = tid >> 5;

    // phase 1: exclusive offset of this block = sum of bsum[0..blockIdx)
    {
        int v = (tid < nb) ? g_bsum[tid] : 0;
        int x = v;
#pragma unroll
        for (int o = 1; o < 32; o <<= 1) {
            int n = __shfl_up_sync(0xffffffffu, x, o);
            if (lane >= o) x += n;
        }
        if (lane == 31) ws[wid] = x;
        __syncthreads();
        if (wid == 0 && lane < 8) {
            int t = ws[lane];
#pragma unroll
            for (int o = 1; o < 8; o <<= 1) {
                int n = __shfl_up_sync(0xffu, t, o);
                if (lane >= o) t += n;
            }
            ws[lane] = t;
        }
        __syncthreads();
        int incl = x + (wid > 0 ? ws[wid - 1] : 0);
        if (tid == blockIdx.x) s_boff = incl - v;   // exclusive
        __syncthreads();
    }
    int boff = s_boff;
    __syncthreads();   // ws reuse barrier

    // phase 2: local exclusive scan of g_cnt for this block's slice
    int i = blockIdx.x * SCAN_B + tid;
    int v = (i < N) ? g_cnt[i] : 0;
    int x = v;
#pragma unroll
    for (int o = 1; o < 32; o <<= 1) {
        int n = __shfl_up_sync(0xffffffffu, x, o);
        if (lane >= o) x += n;
    }
    if (lane == 31) ws[wid] = x;
    __syncthreads();
    if (wid == 0 && lane < 8) {
        int t = ws[lane];
#pragma unroll
        for (int o = 1; o < 8; o <<= 1) {
            int n = __shfl_up_sync(0xffu, t, o);
            if (lane >= o) t += n;
        }
        ws[lane] = t;
    }
    __syncthreads();
    int ex = x - v + (wid > 0 ? ws[wid - 1] : 0) + boff;
    if (i < N) {
        g_rowptr[i] = ex;
        g_cursor[i] = ex;
    }
    if (blockIdx.x == 0 && tid == 0) g_rowptr[N] = E;
}

// ---------------- scatter edges into CSR slots ----------------
__global__ void k_scatter(const int* __restrict__ ei, int E) {
    int e = blockIdx.x * blockDim.x + threadIdx.x;
    if (e < E) {
        int s = ei[e];
        int d = ei[E + e];
        int pos = atomicAdd(&g_cursor[d], 1);
        g_srcs[pos] = s;
        g_w[pos] = g_isd[s] * g_isd[d];
    }
}

// ---------------- GEMM: C[M,128] = A[M,128] @ B[128,128] -------------------
// BK=32 double-buffered, cp.async(B), reg-staged A, f32x2 FMA.
// MODE 0: A=x, B=W1           -> g_h0 = raw
// MODE 1: A=g_aggh, B=g_Wcat  -> out_mu / out_ls = raw + bcat (split)
#define BK 32
template <int MODE>
__global__ void __launch_bounds__(128) k_gemm(const float* __restrict__ Aext,
                                              const float* __restrict__ Bext,
                                              int M,
                                              float* __restrict__ out_mu,
                                              float* __restrict__ out_ls) {
    __shared__ float  As[2][BK][68];
    __shared__ float4 Bs[2][BK * 32];

    const float* A = (MODE == 0) ? Aext : g_aggh;
    const float* B = (MODE == 0) ? Bext : g_Wcat;

    int tid = threadIdx.x;
    int tx = tid & 15;
    int ty = tid >> 4;
    int row0 = blockIdx.x * 64;

    int fr[4], fk[4];
#pragma unroll
    for (int li = 0; li < 4; li++) {
        int f = tid * 4 + li;
        fr[li] = f >> 3;
        fk[li] = (f & 7) * 4;
    }

    unsigned long long accp[8][4];
#pragma unroll
    for (int i = 0; i < 8; i++)
#pragma unroll
        for (int j = 0; j < 4; j++) accp[i][j] = 0ull;

    {
#pragma unroll
        for (int j = 0; j < 8; j++)
            cp_async16(&Bs[0][tid + 128 * j], (const float4*)B + tid + 128 * j);
        cp_commit();
#pragma unroll
        for (int li = 0; li < 4; li++) {
            float4 a = make_float4(0.f, 0.f, 0.f, 0.f);
            if (row0 + fr[li] < M)
                a = *(const float4*)&A[(size_t)(row0 + fr[li]) * D + fk[li]];
            As[0][fk[li] + 0][fr[li]] = a.x;
            As[0][fk[li] + 1][fr[li]] = a.y;
            As[0][fk[li] + 2][fr[li]] = a.z;
            As[0][fk[li] + 3][fr[li]] = a.w;
        }
        cp_wait0();
        __syncthreads();
    }

    for (int k0 = 0; k0 < D; k0 += BK) {
        int s = (k0 / BK) & 1;
        int ns = s ^ 1;
        bool pf = (k0 + BK < D);

        float4 areg[4];
        if (pf) {
#pragma unroll
            for (int j = 0; j < 8; j++)
                cp_async16(&Bs[ns][tid + 128 * j],
                           (const float4*)(B + (size_t)(k0 + BK) * D) + tid + 128 * j);
            cp_commit();
#pragma unroll
            for (int li = 0; li < 4; li++) {
                areg[li] = make_float4(0.f, 0.f, 0.f, 0.f);
                if (row0 + fr[li] < M)
                    areg[li] = *(const float4*)&A[(size_t)(row0 + fr[li]) * D + k0 + BK + fk[li]];
            }
        }

#pragma unroll
        for (int k = 0; k < BK; k++) {
            float4 av0 = *(float4*)&As[s][k][ty * 8];
            float4 av1 = *(float4*)&As[s][k][ty * 8 + 4];
            const float* brow = (const float*)&Bs[s][k * 32];
            unsigned long long bp[4];
#pragma unroll
            for (int j = 0; j < 4; j++)
                bp[j] = *(const unsigned long long*)&brow[tx * 8 + 2 * j];
            float a[8] = {av0.x, av0.y, av0.z, av0.w, av1.x, av1.y, av1.z, av1.w};
#pragma unroll
            for (int i = 0; i < 8; i++) {
                unsigned long long ap = pack2(a[i], a[i]);
#pragma unroll
                for (int j = 0; j < 4; j++)
                    accp[i][j] = fma2(ap, bp[j], accp[i][j]);
            }
        }

        if (pf) {
#pragma unroll
            for (int li = 0; li < 4; li++) {
                As[ns][fk[li] + 0][fr[li]] = areg[li].x;
                As[ns][fk[li] + 1][fr[li]] = areg[li].y;
                As[ns][fk[li] + 2][fr[li]] = areg[li].z;
                As[ns][fk[li] + 3][fr[li]] = areg[li].w;
            }
            cp_wait0();
        }
        __syncthreads();
    }

    int colbase = tx * 8;
#pragma unroll
    for (int i = 0; i < 8; i++) {
        int row = row0 + ty * 8 + i;
        if (row < M) {
            float4 v0, v1;
            unpack2(accp[i][0], v0.x, v0.y);
            unpack2(accp[i][1], v0.z, v0.w);
            unpack2(accp[i][2], v1.x, v1.y);
            unpack2(accp[i][3], v1.z, v1.w);
            if (MODE == 0) {
                *(float4*)&g_h0[(size_t)row * D + colbase]     = v0;
                *(float4*)&g_h0[(size_t)row * D + colbase + 4] = v1;
            } else {
                float4 bi0 = *(const float4*)&g_bcat[colbase];
                float4 bi1 = *(const float4*)&g_bcat[colbase + 4];
                v0.x += bi0.x; v0.y += bi0.y; v0.z += bi0.z; v0.w += bi0.w;
                v1.x += bi1.x; v1.y += bi1.y; v1.z += bi1.z; v1.w += bi1.w;
                if (colbase < DLAT) {
                    *(float4*)&out_mu[(size_t)row * DLAT + colbase]     = v0;
                    *(float4*)&out_mu[(size_t)row * DLAT + colbase + 4] = v1;
                } else {
                    *(float4*)&out_ls[(size_t)row * DLAT + colbase - DLAT]     = v0;
                    *(float4*)&out_ls[(size_t)row * DLAT + colbase - DLAT + 4] = v1;
                }
            }
        }
    }
}

// ---------------- CSR aggregation: warp per node, no output atomics -------
// MODE 0: g_h[i]   = sum_e w*g_h0[src] + invdeg[i]*g_h0[i] + b1  (+ fused BN partials)
// MODE 1: g_aggh[i]= sum_e w*BN(g_h[src]) + invdeg[i]*BN(g_h[i])   (BN+ReLU fused)
template <int MODE>
__global__ void __launch_bounds__(256) k_agg(const float* __restrict__ b1, int N) {
    __shared__ float sh_s[D];
    __shared__ float sh_s2[D];
    if (MODE == 0) {
        if (threadIdx.x < D) { sh_s[threadIdx.x] = 0.f; sh_s2[threadIdx.x] = 0.f; }
        __syncthreads();
    }

    int gwarp = (blockIdx.x * blockDim.x + threadIdx.x) >> 5;
    int lane = threadIdx.x & 31;
    const float* feat = (MODE == 0) ? g_h0 : g_h;

    float4 scf, shf;
    if (MODE == 1) {
        scf = ((const float4*)g_scale)[lane];
        shf = ((const float4*)g_shift)[lane];
    }

    float4 acc = make_float4(0.f, 0.f, 0.f, 0.f);
    bool active = (gwarp < N);
    if (active) {
        int node = gwarp;
        int beg = g_rowptr[node];
        int end = g_rowptr[node + 1];
        float id = g_invdeg[node];

        float4 self = *(const float4*)&feat[(size_t)node * D + lane * 4];
        if (MODE == 1) {
            self.x = fmaxf(fmaf(self.x, scf.x, shf.x), 0.0f);
            self.y = fmaxf(fmaf(self.y, scf.y, shf.y), 0.0f);
            self.z = fmaxf(fmaf(self.z, scf.z, shf.z), 0.0f);
            self.w = fmaxf(fmaf(self.w, scf.w, shf.w), 0.0f);
        }
        acc.x = self.x * id; acc.y = self.y * id;
        acc.z = self.z * id; acc.w = self.w * id;
        if (MODE == 0) {
            float4 bi = *(const float4*)&b1[lane * 4];
            acc.x += bi.x; acc.y += bi.y; acc.z += bi.z; acc.w += bi.w;
        }

        for (int base = beg; base < end; base += 32) {
            int t = base + lane;
            int s = 0; float w = 0.f;
            if (t < end) { s = g_srcs[t]; w = g_w[t]; }
            int m = min(32, end - base);
            for (int j = 0; j < m; j++) {
                int sj = __shfl_sync(0xffffffffu, s, j);
                float wj = __shfl_sync(0xffffffffu, w, j);
                float4 v = *(const float4*)&feat[(size_t)sj * D + lane * 4];
                if (MODE == 1) {
                    v.x = fmaxf(fmaf(v.x, scf.x, shf.x), 0.0f);
                    v.y = fmaxf(fmaf(v.y, scf.y, shf.y), 0.0f);
                    v.z = fmaxf(fmaf(v.z, scf.z, shf.z), 0.0f);
                    v.w = fmaxf(fmaf(v.w, scf.w, shf.w), 0.0f);
                }
                acc.x = fmaf(wj, v.x, acc.x);
                acc.y = fmaf(wj, v.y, acc.y);
                acc.z = fmaf(wj, v.z, acc.z);
                acc.w = fmaf(wj, v.w, acc.w);
            }
        }

        float* out = (MODE == 0) ? g_h : g_aggh;
        *(float4*)&out[(size_t)gwarp * D + lane * 4] = acc;
    }

    if (MODE == 0) {
        if (active) {
            int c = lane * 4;
            atomicAdd(&sh_s[c + 0], acc.x);  atomicAdd(&sh_s2[c + 0], acc.x * acc.x);
            atomicAdd(&sh_s[c + 1], acc.y);  atomicAdd(&sh_s2[c + 1], acc.y * acc.y);
            atomicAdd(&sh_s[c + 2], acc.z);  atomicAdd(&sh_s2[c + 2], acc.z * acc.z);
            atomicAdd(&sh_s[c + 3], acc.w);  atomicAdd(&sh_s2[c + 3], acc.w * acc.w);
        }
        __syncthreads();
        if (threadIdx.x < D) {
            atomicAdd(&g_sum[threadIdx.x], sh_s[threadIdx.x]);
            atomicAdd(&g_sumsq[threadIdx.x], sh_s2[threadIdx.x]);
        }
    }
}

// ---------------- BN finalize ----------------
__global__ void k_bnfin(const float* __restrict__ gamma, const float* __restrict__ beta, int N) {
    int c = threadIdx.x;
    float invN = 1.0f / (float)N;
    float mean = g_sum[c] * invN;
    float var = fmaxf(g_sumsq[c] * invN - mean * mean, 0.0f);
    float sc = gamma[c] * rsqrtf(var + BN_EPS);
    g_scale[c] = sc;
    g_shift[c] = beta[c] - mean * sc;
}

// ---------------- launch ----------------
extern "C" void kernel_launch(void* const* d_in, const int* in_sizes, int n_in,
                              void* d_out, int out_size) {
    const float* x     = (const float*)d_in[0];
    const int*   ei    = (const int*)d_in[1];     // int32
    const float* W1    = (const float*)d_in[2];
    const float* b1    = (const float*)d_in[3];
    const float* gamma = (const float*)d_in[4];
    const float* beta  = (const float*)d_in[5];
    const float* Wmu   = (const float*)d_in[6];
    const float* bmu   = (const float*)d_in[7];
    const float* Wls   = (const float*)d_in[8];
    const float* bls   = (const float*)d_in[9];

    int N = in_sizes[0] / D;
    int E = in_sizes[1] / 2;

    float* out_mu = (float*)d_out;
    float* out_ls = (float*)d_out + (size_t)N * DLAT;

    int init_threads = (N > D * D) ? N : D * D;
    int nb = (N + SCAN_B - 1) / SCAN_B;
    int gemm_blocks = (N + 63) / 64;
    int agg_blocks = (N + 7) / 8;

    // --- fork: gemm0 runs concurrently with the CSR build ---
    cudaStream_t s2;
    cudaStreamCreateWithFlags(&s2, cudaStreamNonBlocking);
    cudaEvent_t eFork, eJoin;
    cudaEventCreateWithFlags(&eFork, cudaEventDisableTiming);
    cudaEventCreateWithFlags(&eJoin, cudaEventDisableTiming);

    cudaEventRecord(eFork, 0);
    cudaStreamWaitEvent(s2, eFork, 0);
    k_gemm<0><<<gemm_blocks, 128, 0, s2>>>(x, W1, N, nullptr, nullptr);
    cudaEventRecord(eJoin, s2);

    // CSR build on the capture stream (independent of gemm0)
    k_init<<<(init_threads + 255) / 256, 256>>>(Wmu, Wls, bmu, bls, N);
    k_count<<<(E + 255) / 256, 256>>>(ei, E);
    k_scanA<<<nb, SCAN_B>>>(N);
    k_scanBC<<<nb, SCAN_B>>>(nb, E, N);
    k_scatter<<<(E + 255) / 256, 256>>>(ei, E);

    // join: agg0 needs both gemm0 (g_h0) and the CSR
    cudaStreamWaitEvent(0, eJoin, 0);

    // --- conv1 aggregation (+fused BN stats) ---
    k_agg<0><<<agg_blocks, 256>>>(b1, N);

    // --- BatchNorm finalize (apply fused into k_agg<1>) ---
    k_bnfin<<<1, 128>>>(gamma, beta, N);

    // --- conv2: aggregate BN(h) (fused), then fused [Wmu|Wls] GEMM ---
    k_agg<1><<<agg_blocks, 256>>>(nullptr, N);
    k_gemm<1><<<gemm_blocks, 128>>>(nullptr, nullptr, N, out_mu, out_ls);

    cudaEventDestroy(eFork);
    cudaEventDestroy(eJoin);
    cudaStreamDestroy(s2);
}

// round 10
// speedup vs baseline: 1.2814x; 1.2244x over previous
#include <cuda_runtime.h>
#include <cuda_bf16.h>

// ---------------- problem constants ----------------
#define NMAX 50000
#define EMAX 800000
#define D    128
#define DLAT 64
#define BN_EPS 1e-5f
#define SCAN_B 256
#define NBLK ((NMAX + SCAN_B - 1) / SCAN_B)

typedef unsigned int uint32;

// ---------------- bf16 split/pack helpers ----------------
// pack two floats as bf16x2 (low half = x, high half = y)
__device__ __forceinline__ uint32 bf16x2_of(float x, float y) {
    uint32 r;
    asm("cvt.rn.bf16x2.f32 %0, %1, %2;" : "=r"(r) : "f"(y), "f"(x));
    return r;
}
// split (x,y) into hi bf16x2 and lo (residual) bf16x2
__device__ __forceinline__ void split_pack(float x, float y, uint32& hi, uint32& lo) {
    hi = bf16x2_of(x, y);
    float hx = __uint_as_float(hi << 16);
    float hy = __uint_as_float(hi & 0xFFFF0000u);
    lo = bf16x2_of(x - hx, y - hy);
}

// mma.sync m16n8k16 row.col bf16 -> fp32 accum
__device__ __forceinline__ void mma_bf16(float& c0, float& c1, float& c2, float& c3,
                                         uint32 a0, uint32 a1, uint32 a2, uint32 a3,
                                         uint32 b0, uint32 b1) {
    asm volatile(
        "mma.sync.aligned.m16n8k16.row.col.f32.bf16.bf16.f32 "
        "{%0,%1,%2,%3}, {%4,%5,%6,%7}, {%8,%9}, {%0,%1,%2,%3};"
        : "+f"(c0), "+f"(c1), "+f"(c2), "+f"(c3)
        : "r"(a0), "r"(a1), "r"(a2), "r"(a3), "r"(b0), "r"(b1));
}

// ---------------- scratch (device globals; no allocation) ----------------
__device__ int    g_cnt[NMAX];
__device__ int    g_rowptr[NMAX + 1];
__device__ int    g_cursor[NMAX];
__device__ int    g_srcs[EMAX];
__device__ float  g_w[EMAX];
__device__ int    g_bsum[NBLK];
__device__ float  g_isd[NMAX];
__device__ float  g_invdeg[NMAX];
__device__ float  g_h0[(size_t)NMAX * D];
__device__ float  g_h [(size_t)NMAX * D];
__device__ float  g_aggh[(size_t)NMAX * D];
__device__ float  g_sum[D];
__device__ float  g_sumsq[D];
__device__ float  g_scale[D];
__device__ float  g_shift[D];
__device__ float  g_bcat[D];
// W matrices pre-split hi/lo, pre-packed in m16n8k16 B-fragment order:
// plane 0 = hi (8192 u32), plane 1 = lo (8192 u32)
__device__ uint32 g_BpW1[2 * 8192];
__device__ uint32 g_BpWc[2 * 8192];

// ---------------- init: zero counters/accums, pack W1/Wcat hi-lo ----------
// B-fragment index: i = ntile*512 + kchunk*64 + lane*2 + reg
//   lane: g = lane>>2 (n within tile), tig = lane&3; kpair = reg*4+tig
//   k = kchunk*16 + kpair*2 ; n = ntile*8 + g ; value = {W[k][n], W[k+1][n]}
__global__ void k_init(const float* __restrict__ W1,
                       const float* __restrict__ Wmu, const float* __restrict__ Wls,
                       const float* __restrict__ bmu, const float* __restrict__ bls,
                       int N) {
    int i = blockIdx.x * blockDim.x + threadIdx.x;
    if (i < N) g_cnt[i] = 0;
    if (i < D) {
        g_sum[i] = 0.0f;
        g_sumsq[i] = 0.0f;
        g_bcat[i] = (i < DLAT) ? bmu[i] : bls[i - DLAT];
    }
    if (i < 8192) {
        int ntile = i >> 9;
        int r = i & 511;
        int kchunk = r >> 6;
        int r2 = r & 63;
        int lane = r2 >> 1;
        int reg = r2 & 1;
        int g = lane >> 2, tig = lane & 3;
        int k = kchunk * 16 + (reg * 4 + tig) * 2;
        int n = ntile * 8 + g;

        float w0 = W1[k * D + n];
        float w1 = W1[(k + 1) * D + n];
        uint32 h, l;
        split_pack(w0, w1, h, l);
        g_BpW1[i] = h;
        g_BpW1[8192 + i] = l;

        float c0 = (n < DLAT) ? Wmu[k * DLAT + n]       : Wls[k * DLAT + n - DLAT];
        float c1 = (n < DLAT) ? Wmu[(k + 1) * DLAT + n] : Wls[(k + 1) * DLAT + n - DLAT];
        split_pack(c0, c1, h, l);
        g_BpWc[i] = h;
        g_BpWc[8192 + i] = l;
    }
}

// ---------------- degree count over dst ----------------
__global__ void k_count(const int* __restrict__ ei, int E) {
    int e = blockIdx.x * blockDim.x + threadIdx.x;
    if (e < E) atomicAdd(&g_cnt[ei[E + e]], 1);
}

// ---------------- scan phase A: block sums + degree-derived values ----------
__global__ void __launch_bounds__(SCAN_B) k_scanA(int N) {
    __shared__ int ws[8];
    int i = blockIdx.x * SCAN_B + threadIdx.x;
    int v = (i < N) ? g_cnt[i] : 0;
    if (i < N) {
        float d = (float)v + 1.0f;
        g_isd[i] = rsqrtf(d);
        g_invdeg[i] = 1.0f / d;
    }
    int lane = threadIdx.x & 31, wid = threadIdx.x >> 5;
    int r = v;
#pragma unroll
    for (int o = 16; o; o >>= 1) r += __shfl_down_sync(0xffffffffu, r, o);
    if (lane == 0) ws[wid] = r;
    __syncthreads();
    if (threadIdx.x < 8) {
        int t = ws[threadIdx.x];
#pragma unroll
        for (int o = 4; o; o >>= 1) t += __shfl_down_sync(0xffu, t, o);
        if (threadIdx.x == 0) g_bsum[blockIdx.x] = t;
    }
}

// ---------------- scan phase B+C merged ----------
__global__ void __launch_bounds__(SCAN_B) k_scanBC(int nb, int E, int N) {
    __shared__ int ws[8];
    __shared__ int s_boff;
    int tid = threadIdx.x;
    int lane = tid & 31, wid = tid >> 5;

    {
        int v = (tid < nb) ? g_bsum[tid] : 0;
        int x = v;
#pragma unroll
        for (int o = 1; o < 32; o <<= 1) {
            int n = __shfl_up_sync(0xffffffffu, x, o);
            if (lane >= o) x += n;
        }
        if (lane == 31) ws[wid] = x;
        __syncthreads();
        if (wid == 0 && lane < 8) {
            int t = ws[lane];
#pragma unroll
            for (int o = 1; o < 8; o <<= 1) {
                int n = __shfl_up_sync(0xffu, t, o);
                if (lane >= o) t += n;
            }
            ws[lane] = t;
        }
        __syncthreads();
        int incl = x + (wid > 0 ? ws[wid - 1] : 0);
        if (tid == blockIdx.x) s_boff = incl - v;
        __syncthreads();
    }
    int boff = s_boff;
    __syncthreads();

    int i = blockIdx.x * SCAN_B + tid;
    int v = (i < N) ? g_cnt[i] : 0;
    int x = v;
#pragma unroll
    for (int o = 1; o < 32; o <<= 1) {
        int n = __shfl_up_sync(0xffffffffu, x, o);
        if (lane >= o) x += n;
    }
    if (lane == 31) ws[wid] = x;
    __syncthreads();
    if (wid == 0 && lane < 8) {
        int t = ws[lane];
#pragma unroll
        for (int o = 1; o < 8; o <<= 1) {
            int n = __shfl_up_sync(0xffu, t, o);
            if (lane >= o) t += n;
        }
        ws[lane] = t;
    }
    __syncthreads();
    int ex = x - v + (wid > 0 ? ws[wid - 1] : 0) + boff;
    if (i < N) {
        g_rowptr[i] = ex;
        g_cursor[i] = ex;
    }
    if (blockIdx.x == 0 && tid == 0) g_rowptr[N] = E;
}

// ---------------- scatter edges into CSR slots ----------------
__global__ void k_scatter(const int* __restrict__ ei, int E) {
    int e = blockIdx.x * blockDim.x + threadIdx.x;
    if (e < E) {
        int s = ei[e];
        int d = ei[E + e];
        int pos = atomicAdd(&g_cursor[d], 1);
        g_srcs[pos] = s;
        g_w[pos] = g_isd[s] * g_isd[d];
    }
}

// ---------------- tensor-core GEMM: C[M,128] = A[M,128] @ W[128,128] -------
// 3-pass bf16 hi/lo split (Ahi*Bhi + Ahi*Blo + Alo*Bhi), fp32 accumulate.
// Block: 256 threads, tile 64 rows x 128 cols. Dynamic smem 96 KB:
//   [0,4096)      A hi fragments (u32)
//   [4096,8192)   A lo fragments
//   [8192,16384)  B hi fragments
//   [16384,24576) B lo fragments
// MODE 0: A=x        -> g_h0 = raw
// MODE 1: A=g_aggh   -> out_mu / out_ls = raw + bcat (split at col 64)
template <int MODE>
__global__ void __launch_bounds__(256) k_gemm_tc(const float* __restrict__ Aext, int M,
                                                 float* __restrict__ out_mu,
                                                 float* __restrict__ out_ls) {
    extern __shared__ uint32 sm[];
    uint32* sAh = sm;
    uint32* sAl = sm + 4096;
    uint32* sBh = sm + 8192;
    uint32* sBl = sm + 16384;

    const float*  A  = (MODE == 0) ? Aext : g_aggh;
    const uint32* Bp = (MODE == 0) ? g_BpW1 : g_BpWc;

    int tid = threadIdx.x;
    int row0 = blockIdx.x * 64;

    // ---- copy pre-packed B (hi+lo = 16384 u32 = 4096 uint4) ----
#pragma unroll
    for (int it = 0; it < 16; it++) {
        int idx = tid + 256 * it;
        ((uint4*)sBh)[idx] = ((const uint4*)Bp)[idx];
    }

    // ---- convert A tile (64 x 128 fp32) to hi/lo fragment layout ----
    // a-fragment: lane g=rin&7 quad, tig = pair&3;
    // reg bit1 = k-octet (cols>=8 within 16), bit0 = row-half (rin>=8)
#pragma unroll
    for (int it = 0; it < 16; it++) {
        int p = tid + 256 * it;          // pair index, 64 rows x 64 col-pairs
        int row = p >> 6, cp = p & 63;
        int gr = row0 + row;
        float2 v = make_float2(0.f, 0.f);
        if (gr < M) v = *(const float2*)&A[(size_t)gr * D + 2 * cp];
        uint32 h, l;
        split_pack(v.x, v.y, h, l);
        int mtile = row >> 4, rin = row & 15;
        int kchunk = cp >> 3, pc = cp & 7;
        int tig = pc & 3;
        int reg = ((pc >> 2) << 1) | (rin >> 3);
        int lfr = ((rin & 7) << 2) | tig;
        int dest = mtile * 1024 + kchunk * 128 + lfr * 4 + reg;
        sAh[dest] = h;
        sAl[dest] = l;
    }
    __syncthreads();

    // ---- mainloop: no barriers, pure LDS + HMMA ----
    int wid = tid >> 5, lane = tid & 31;
    int mw = wid & 1;       // m position: rows mw*32 (mtiles 2mw, 2mw+1)
    int nw = wid >> 1;      // n position: cols nw*32 (ntiles 4nw..4nw+3)

    float c[2][4][4];
#pragma unroll
    for (int i = 0; i < 2; i++)
#pragma unroll
        for (int j = 0; j < 4; j++)
#pragma unroll
            for (int q = 0; q < 4; q++) c[i][j][q] = 0.0f;

#pragma unroll
    for (int kc = 0; kc < 8; kc++) {
        int aoff = (2 * mw) * 1024 + kc * 128 + lane * 4;
        uint4 ah0 = *(const uint4*)&sAh[aoff];
        uint4 ah1 = *(const uint4*)&sAh[aoff + 1024];
        uint4 al0 = *(const uint4*)&sAl[aoff];
        uint4 al1 = *(const uint4*)&sAl[aoff + 1024];
#pragma unroll
        for (int nt = 0; nt < 4; nt++) {
            int boff = (nw * 4 + nt) * 512 + kc * 64 + lane * 2;
            uint2 bh = *(const uint2*)&sBh[boff];
            uint2 bl = *(const uint2*)&sBl[boff];
            // hi*hi
            mma_bf16(c[0][nt][0], c[0][nt][1], c[0][nt][2], c[0][nt][3],
                     ah0.x, ah0.y, ah0.z, ah0.w, bh.x, bh.y);
            mma_bf16(c[1][nt][0], c[1][nt][1], c[1][nt][2], c[1][nt][3],
                     ah1.x, ah1.y, ah1.z, ah1.w, bh.x, bh.y);
            // hi*lo
            mma_bf16(c[0][nt][0], c[0][nt][1], c[0][nt][2], c[0][nt][3],
                     ah0.x, ah0.y, ah0.z, ah0.w, bl.x, bl.y);
            mma_bf16(c[1][nt][0], c[1][nt][1], c[1][nt][2], c[1][nt][3],
                     ah1.x, ah1.y, ah1.z, ah1.w, bl.x, bl.y);
            // lo*hi
            mma_bf16(c[0][nt][0], c[0][nt][1], c[0][nt][2], c[0][nt][3],
                     al0.x, al0.y, al0.z, al0.w, bh.x, bh.y);
            mma_bf16(c[1][nt][0], c[1][nt][1], c[1][nt][2], c[1][nt][3],
                     al1.x, al1.y, al1.z, al1.w, bh.x, bh.y);
        }
    }

    // ---- epilogue: c0=(g,2tig) c1=(g,2tig+1) c2=(g+8,2tig) c3=(g+8,2tig+1)
    int g = lane >> 2, tig = lane & 3;
#pragma unroll
    for (int mt = 0; mt < 2; mt++) {
        int r = row0 + (2 * mw + mt) * 16 + g;
#pragma unroll
        for (int nt = 0; nt < 4; nt++) {
            int col = (nw * 4 + nt) * 8 + 2 * tig;
            float2 v01 = make_float2(c[mt][nt][0], c[mt][nt][1]);
            float2 v23 = make_float2(c[mt][nt][2], c[mt][nt][3]);
            if (MODE == 0) {
                if (r < M)     *(float2*)&g_h0[(size_t)r * D + col] = v01;
                if (r + 8 < M) *(float2*)&g_h0[(size_t)(r + 8) * D + col] = v23;
            } else {
                float2 bc = *(const float2*)&g_bcat[col];
                v01.x += bc.x; v01.y += bc.y;
                v23.x += bc.x; v23.y += bc.y;
                if (col < DLAT) {
                    if (r < M)     *(float2*)&out_mu[(size_t)r * DLAT + col] = v01;
                    if (r + 8 < M) *(float2*)&out_mu[(size_t)(r + 8) * DLAT + col] = v23;
                } else {
                    if (r < M)     *(float2*)&out_ls[(size_t)r * DLAT + col - DLAT] = v01;
                    if (r + 8 < M) *(float2*)&out_ls[(size_t)(r + 8) * DLAT + col - DLAT] = v23;
                }
            }
        }
    }
}

// ---------------- CSR aggregation: warp per node, no output atomics -------
// MODE 0: g_h[i]   = sum_e w*g_h0[src] + invdeg[i]*g_h0[i] + b1  (+ fused BN partials)
// MODE 1: g_aggh[i]= sum_e w*BN(g_h[src]) + invdeg[i]*BN(g_h[i])   (BN+ReLU fused)
template <int MODE>
__global__ void __launch_bounds__(256) k_agg(const float* __restrict__ b1, int N) {
    __shared__ float sh_s[D];
    __shared__ float sh_s2[D];
    if (MODE == 0) {
        if (threadIdx.x < D) { sh_s[threadIdx.x] = 0.f; sh_s2[threadIdx.x] = 0.f; }
        __syncthreads();
    }

    int gwarp = (blockIdx.x * blockDim.x + threadIdx.x) >> 5;
    int lane = threadIdx.x & 31;
    const float* feat = (MODE == 0) ? g_h0 : g_h;

    float4 scf, shf;
    if (MODE == 1) {
        scf = ((const float4*)g_scale)[lane];
        shf = ((const float4*)g_shift)[lane];
    }

    float4 acc = make_float4(0.f, 0.f, 0.f, 0.f);
    bool active = (gwarp < N);
    if (active) {
        int node = gwarp;
        int beg = g_rowptr[node];
        int end = g_rowptr[node + 1];
        float id = g_invdeg[node];

        float4 self = *(const float4*)&feat[(size_t)node * D + lane * 4];
        if (MODE == 1) {
            self.x = fmaxf(fmaf(self.x, scf.x, shf.x), 0.0f);
            self.y = fmaxf(fmaf(self.y, scf.y, shf.y), 0.0f);
            self.z = fmaxf(fmaf(self.z, scf.z, shf.z), 0.0f);
            self.w = fmaxf(fmaf(self.w, scf.w, shf.w), 0.0f);
        }
        acc.x = self.x * id; acc.y = self.y * id;
        acc.z = self.z * id; acc.w = self.w * id;
        if (MODE == 0) {
            float4 bi = *(const float4*)&b1[lane * 4];
            acc.x += bi.x; acc.y += bi.y; acc.z += bi.z; acc.w += bi.w;
        }

        for (int base = beg; base < end; base += 32) {
            int t = base + lane;
            int s = 0; float w = 0.f;
            if (t < end) { s = g_srcs[t]; w = g_w[t]; }
            int m = min(32, end - base);
            for (int j = 0; j < m; j++) {
                int sj = __shfl_sync(0xffffffffu, s, j);
                float wj = __shfl_sync(0xffffffffu, w, j);
                float4 v = *(const float4*)&feat[(size_t)sj * D + lane * 4];
                if (MODE == 1) {
                    v.x = fmaxf(fmaf(v.x, scf.x, shf.x), 0.0f);
                    v.y = fmaxf(fmaf(v.y, scf.y, shf.y), 0.0f);
                    v.z = fmaxf(fmaf(v.z, scf.z, shf.z), 0.0f);
                    v.w = fmaxf(fmaf(v.w, scf.w, shf.w), 0.0f);
                }
                acc.x = fmaf(wj, v.x, acc.x);
                acc.y = fmaf(wj, v.y, acc.y);
                acc.z = fmaf(wj, v.z, acc.z);
                acc.w = fmaf(wj, v.w, acc.w);
            }
        }

        float* out = (MODE == 0) ? g_h : g_aggh;
        *(float4*)&out[(size_t)gwarp * D + lane * 4] = acc;
    }

    if (MODE == 0) {
        if (active) {
            int c = lane * 4;
            atomicAdd(&sh_s[c + 0], acc.x);  atomicAdd(&sh_s2[c + 0], acc.x * acc.x);
            atomicAdd(&sh_s[c + 1], acc.y);  atomicAdd(&sh_s2[c + 1], acc.y * acc.y);
            atomicAdd(&sh_s[c + 2], acc.z);  atomicAdd(&sh_s2[c + 2], acc.z * acc.z);
            atomicAdd(&sh_s[c + 3], acc.w);  atomicAdd(&sh_s2[c + 3], acc.w * acc.w);
        }
        __syncthreads();
        if (threadIdx.x < D) {
            atomicAdd(&g_sum[threadIdx.x], sh_s[threadIdx.x]);
            atomicAdd(&g_sumsq[threadIdx.x], sh_s2[threadIdx.x]);
        }
    }
}

// ---------------- BN finalize ----------------
__global__ void k_bnfin(const float* __restrict__ gamma, const float* __restrict__ beta, int N) {
    int c = threadIdx.x;
    float invN = 1.0f / (float)N;
    float mean = g_sum[c] * invN;
    float var = fmaxf(g_sumsq[c] * invN - mean * mean, 0.0f);
    float sc = gamma[c] * rsqrtf(var + BN_EPS);
    g_scale[c] = sc;
    g_shift[c] = beta[c] - mean * sc;
}

// ---------------- launch ----------------
extern "C" void kernel_launch(void* const* d_in, const int* in_sizes, int n_in,
                              void* d_out, int out_size) {
    const float* x     = (const float*)d_in[0];
    const int*   ei    = (const int*)d_in[1];     // int32
    const float* W1    = (const float*)d_in[2];
    const float* b1    = (const float*)d_in[3];
    const float* gamma = (const float*)d_in[4];
    const float* beta  = (const float*)d_in[5];
    const float* Wmu   = (const float*)d_in[6];
    const float* bmu   = (const float*)d_in[7];
    const float* Wls   = (const float*)d_in[8];
    const float* bls   = (const float*)d_in[9];

    int N = in_sizes[0] / D;
    int E = in_sizes[1] / 2;

    float* out_mu = (float*)d_out;
    float* out_ls = (float*)d_out + (size_t)N * DLAT;

    int nb = (N + SCAN_B - 1) / SCAN_B;
    int gemm_blocks = (N + 63) / 64;
    int agg_blocks = (N + 7) / 8;

    static bool attr_done = false;
    if (!attr_done) {
        cudaFuncSetAttribute(k_gemm_tc<0>, cudaFuncAttributeMaxDynamicSharedMemorySize, 98304);
        cudaFuncSetAttribute(k_gemm_tc<1>, cudaFuncAttributeMaxDynamicSharedMemorySize, 98304);
        attr_done = true;
    }

    // --- k_init first (gemm0 needs packed W1), then fork gemm0 vs CSR ---
    k_init<<<(N + 255) / 256, 256>>>(W1, Wmu, Wls, bmu, bls, N);

    cudaStream_t s2;
    cudaStreamCreateWithFlags(&s2, cudaStreamNonBlocking);
    cudaEvent_t eFork, eJoin;
    cudaEventCreateWithFlags(&eFork, cudaEventDisableTiming);
    cudaEventCreateWithFlags(&eJoin, cudaEventDisableTiming);

    cudaEventRecord(eFork, 0);
    cudaStreamWaitEvent(s2, eFork, 0);
    k_gemm_tc<0><<<gemm_blocks, 256, 98304, s2>>>(x, N, nullptr, nullptr);
    cudaEventRecord(eJoin, s2);

    // CSR build on the capture stream (independent of gemm0)
    k_count<<<(E + 255) / 256, 256>>>(ei, E);
    k_scanA<<<nb, SCAN_B>>>(N);
    k_scanBC<<<nb, SCAN_B>>>(nb, E, N);
    k_scatter<<<(E + 255) / 256, 256>>>(ei, E);

    // join: agg0 needs both gemm0 (g_h0) and the CSR
    cudaStreamWaitEvent(0, eJoin, 0);

    // --- conv1 aggregation (+fused BN stats) ---
    k_agg<0><<<agg_blocks, 256>>>(b1, N);

    // --- BatchNorm finalize (apply fused into k_agg<1>) ---
    k_bnfin<<<1, 128>>>(gamma, beta, N);

    // --- conv2: aggregate BN(h) (fused), then fused [Wmu|Wls] tensor GEMM ---
    k_agg<1><<<agg_blocks, 256>>>(nullptr, N);
    k_gemm_tc<1><<<gemm_blocks, 256, 98304>>>(nullptr, N, out_mu, out_ls);

    cudaEventDestroy(eFork);
    cudaEventDestroy(eJoin);
    cudaStreamDestroy(s2);
}